// round 3
// baseline (speedup 1.0000x reference)
#include <cuda_runtime.h>
#include <cstdint>

// Problem constants (fixed shapes per metadata): x = (8,32,256,256) fp32, K=3
#define PLANES 256            // B*C = 8*32
#define H      256
#define W      256
#define HO     254
#define WO     254
#define N_ELEM (PLANES * H * W)     // 16,777,216
#define N4     (N_ELEM / 4)

// Histogram kernel config: per-thread private byte counters (no atomics).
#define HB 1024               // hist blocks
#define HT 128                // hist threads/block
// elements per thread = N_ELEM / (HB*HT) = 128  (< 255 -> u8 counters safe)
#define HF4 32                // float4 loads per thread
#define TPAD 260              // padded bytes per thread (65 words: bank = (lane + v>>2)&31)

#define TW 64                 // pool output tile width
#define TH 32                 // pool output tile height
#define IN_W (TW + 2)         // 66
#define IN_H (TH + 2)         // 34

__device__ int g_counts[256];

// ---------------------------------------------------------------------------
// Kernel 1: zero the global histogram (device globals persist across graph
// replays, so this must run every replay, before hist's block reductions).
// ---------------------------------------------------------------------------
__global__ void zero_counts_kernel() {
    g_counts[threadIdx.x] = 0;
}

// ---------------------------------------------------------------------------
// Kernel 2: 256-bin histogram, per-thread-private byte counters in shared.
// No shared atomics: each thread owns a 256-byte (padded to 260) counter
// array; increments are plain LDS.U8/STS.U8. The x65-word stride makes
// bank = (lane + (v>>2)) & 31, so the all-lanes-equal-value case is
// conflict-free; random values give ~birthday-level conflicts (~3).
// Epilogue: 64 threads each reduce one 4-bin group across all 128 thread
// columns (conflict-free LDS.32, dp4a byte sums) and atomicAdd to global.
// ---------------------------------------------------------------------------
__global__ void hist_kernel(const float4* __restrict__ x) {
    __shared__ unsigned char s_c[HT * TPAD];   // 33,280 B

    const int tid = threadIdx.x;

    // zero counters (as int4: 33280/16 = 2080 vec stores)
    int4* s_v = (int4*)s_c;
    #pragma unroll
    for (int i = tid; i < HT * TPAD / 16; i += HT)
        s_v[i] = make_int4(0, 0, 0, 0);
    __syncthreads();

    unsigned char* my = s_c + tid * TPAD;
    const float4* base = x + (size_t)blockIdx.x * (HT * HF4);

    #pragma unroll 4
    for (int j = 0; j < HF4; j++) {
        float4 v = base[j * HT + tid];
        my[((int)v.x) & 255]++;
        my[((int)v.y) & 255]++;
        my[((int)v.z) & 255]++;
        my[((int)v.w) & 255]++;
    }
    __syncthreads();

    // Reduce: thread k (k<64) sums bin group [4k..4k+3] over 128 columns.
    if (tid < 64) {
        const unsigned int* s_w = (const unsigned int*)s_c;
        unsigned int s0 = 0u, s1 = 0u, s2 = 0u, s3 = 0u;
        #pragma unroll 8
        for (int t = 0; t < HT; t++) {
            unsigned int w = s_w[t * (TPAD / 4) + tid];
            s0 = __dp4a(w, 0x00000001u, s0);
            s1 = __dp4a(w, 0x00000100u, s1);
            s2 = __dp4a(w, 0x00010000u, s2);
            s3 = __dp4a(w, 0x01000000u, s3);
        }
        atomicAdd(&g_counts[4 * tid + 0], (int)s0);
        atomicAdd(&g_counts[4 * tid + 1], (int)s1);
        atomicAdd(&g_counts[4 * tid + 2], (int)s2);
        atomicAdd(&g_counts[4 * tid + 3], (int)s3);
    }
}

// ---------------------------------------------------------------------------
// Kernel 3: entropy pool. Per block: 64x32 output tile of one plane.
// Shared tile holds packed (count<<8 | value). Count clamped to 0xFFFFFF:
// safe because sum(counts) = 2^24, so at most one count can reach 2^24 and
// no other count can tie the clamped value.
// Tie-break: strict '<' scan in di-outer/dj-inner order == jnp.argmin first-min.
// ---------------------------------------------------------------------------
__global__ void pool_kernel(const float* __restrict__ x, float* __restrict__ out) {
    __shared__ int s_cnt[256];
    __shared__ unsigned int s_p[IN_H * IN_W];

    const int tid = threadIdx.x;
    s_cnt[tid] = g_counts[tid];            // blockDim.x == 256
    __syncthreads();

    const int plane = blockIdx.z;
    const int ty0 = blockIdx.y * TH;
    const int tx0 = blockIdx.x * TW;
    const float* xp = x + (size_t)plane * (H * W);

    for (int i = tid; i < IN_H * IN_W; i += 256) {
        int r = i / IN_W, c = i - r * IN_W;
        int gr = ty0 + r, gc = tx0 + c;
        unsigned int p = 0xFFFFFFFFu;
        if (gr < H && gc < W) {
            int v = ((int)xp[gr * W + gc]) & 255;
            unsigned int cnt = (unsigned int)s_cnt[v];
            if (cnt > 0xFFFFFFu) cnt = 0xFFFFFFu;
            p = (cnt << 8) | (unsigned int)v;
        }
        s_p[i] = p;
    }
    __syncthreads();

    const int tx  = tid & (TW - 1);        // 0..63
    const int tyb = tid >> 6;              // 0..3
    const int ocol = tx0 + tx;
    if (ocol >= WO) return;

    float* op = out + (size_t)plane * (HO * WO);
    #pragma unroll
    for (int rr = 0; rr < TH / 4; rr++) {
        const int ry = tyb * (TH / 4) + rr;     // 0..31
        const int orow = ty0 + ry;
        if (orow >= HO) break;
        const unsigned int* row0 = &s_p[ry * IN_W + tx];
        unsigned int bestc = 0xFFFFFFFFu;
        unsigned int bestp = 0;
        #pragma unroll
        for (int di = 0; di < 3; di++) {
            #pragma unroll
            for (int dj = 0; dj < 3; dj++) {
                unsigned int p = row0[di * IN_W + dj];
                unsigned int c = p >> 8;
                if (c < bestc) { bestc = c; bestp = p; }
            }
        }
        op[orow * WO + ocol] = (float)(bestp & 0xFFu);
    }
}

// ---------------------------------------------------------------------------
extern "C" void kernel_launch(void* const* d_in, const int* in_sizes, int n_in,
                              void* d_out, int out_size) {
    const float* x = (const float*)d_in[0];
    float* out = (float*)d_out;

    zero_counts_kernel<<<1, 256>>>();
    hist_kernel<<<HB, HT>>>((const float4*)x);

    dim3 grid((WO + TW - 1) / TW, (HO + TH - 1) / TH, PLANES);  // (4, 8, 256)
    pool_kernel<<<grid, 256>>>(x, out);
}

// round 4
// speedup vs baseline: 1.3031x; 1.3031x over previous
#include <cuda_runtime.h>
#include <cstdint>

// Problem constants (fixed shapes): x = (8,32,256,256) fp32, K=3
#define PLANES 256            // B*C
#define H      256
#define W      256
#define HO     254
#define WO     254
#define N_ELEM (PLANES * H * W)     // 16,777,216
#define N4     (N_ELEM / 4)

// Hist config (lane-interleaved shared-atomic version, proven in R1)
#define HB 1024               // hist blocks
#define HTH 256               // hist threads/block
#define HITER (N4 / (HB * HTH))   // 16 float4 per thread

// Pool config
#define TW 64                 // output tile width
#define TH 32                 // output tile height
#define IN_W  66              // TW + 2
#define IN_H  34              // TH + 2
#define IN_WP 68              // padded row stride (17 uint4)

__device__ int g_counts[256];
__device__ int g_partial[256 * HB];   // [bin][block], 1 MB scratch

// ---------------------------------------------------------------------------
// Kernel 1: 256-bin histogram. 32 lane-interleaved shared sub-histograms
// (addr = bin*32 + lane) -> every warp-atomic is bank-conflict-free ATOMS.
// Per-block result written to g_partial (plain STG; no zeroing needed).
// ---------------------------------------------------------------------------
__global__ void __launch_bounds__(HTH) hist_kernel(const float4* __restrict__ x) {
    __shared__ int s_h[256 * 32];   // 32 KB
    const int tid = threadIdx.x;
    #pragma unroll
    for (int i = tid; i < 256 * 32; i += HTH) s_h[i] = 0;
    __syncthreads();

    const int lane = tid & 31;
    const float4* base = x + (size_t)blockIdx.x * (HTH * HITER);
    #pragma unroll 4
    for (int j = 0; j < HITER; j++) {
        float4 v = base[j * HTH + tid];
        atomicAdd(&s_h[(((int)v.x) & 255) * 32 + lane], 1);
        atomicAdd(&s_h[(((int)v.y) & 255) * 32 + lane], 1);
        atomicAdd(&s_h[(((int)v.z) & 255) * 32 + lane], 1);
        atomicAdd(&s_h[(((int)v.w) & 255) * 32 + lane], 1);
    }
    __syncthreads();

    // thread t reduces bin t's 32 lane-copies (staggered: conflict-free)
    int sum = 0;
    #pragma unroll
    for (int j = 0; j < 32; j++) {
        int i = (j + lane) & 31;
        sum += s_h[tid * 32 + i];
    }
    g_partial[tid * HB + blockIdx.x] = sum;     // coalesced across bins? per-bin row
}

// ---------------------------------------------------------------------------
// Kernel 2: finalize — g_counts[bin] = sum over HB partials (overwrite; no
// zero kernel needed, deterministic across graph replays).
// ---------------------------------------------------------------------------
__global__ void __launch_bounds__(128) finalize_kernel() {
    const int bin = blockIdx.x;
    const int tid = threadIdx.x;
    int s = 0;
    #pragma unroll
    for (int k = 0; k < HB / 128; k++)
        s += g_partial[bin * HB + k * 128 + tid];
    #pragma unroll
    for (int o = 16; o; o >>= 1) s += __shfl_down_sync(0xFFFFFFFFu, s, o);
    __shared__ int ws[4];
    if ((tid & 31) == 0) ws[tid >> 5] = s;
    __syncthreads();
    if (tid == 0) g_counts[bin] = ws[0] + ws[1] + ws[2] + ws[3];
}

// ---------------------------------------------------------------------------
// Kernel 3: entropy pool. 64x32 output tile/block, 8 outputs/thread.
// Tile of packed (count<<8 | value) words, padded row stride 68 for vector
// LDS. Separable first-min (rows then cols) preserves argmin first-occurrence
// tie-break; compares are on count only (strict <, earlier-kept).
// Count clamp to 0xFFFFFF safe: sum(counts)=2^24 so no tie with a clamped max.
// ---------------------------------------------------------------------------
__device__ __forceinline__ void fmin2(unsigned& c0, unsigned& p0,
                                      unsigned c1, unsigned p1) {
    if (c1 < c0) { c0 = c1; p0 = p1; }
}

__global__ void __launch_bounds__(256) pool_kernel(const float* __restrict__ x,
                                                   float* __restrict__ out) {
    __shared__ int s_cnt[256];
    __shared__ unsigned int s_p[IN_H * IN_WP + 2];  // +2: pad for vec reads

    const int tid = threadIdx.x;
    s_cnt[tid] = g_counts[tid];
    __syncthreads();

    const int plane = blockIdx.z;
    const int ty0 = blockIdx.y * TH;
    const int tx0 = blockIdx.x * TW;
    const float* xp = x + (size_t)plane * (H * W);

    for (int i = tid; i < IN_H * IN_W; i += 256) {
        int r = i / IN_W, c = i - r * IN_W;
        int gr = ty0 + r, gc = tx0 + c;
        unsigned int p = 0xFFFFFFFFu;
        if (gr < H && gc < W) {
            int v = ((int)xp[gr * W + gc]) & 255;
            unsigned int cnt = (unsigned int)s_cnt[v];
            if (cnt > 0xFFFFFFu) cnt = 0xFFFFFFu;
            p = (cnt << 8) | (unsigned int)v;
        }
        s_p[r * IN_WP + c] = p;
    }
    __syncthreads();

    const int rg = tid >> 4;        // 0..15 -> output rows 2*rg, 2*rg+1
    const int cg = tid & 15;        // 0..15 -> output cols 4*cg..4*cg+3
    const int r0 = rg * 2;

    const uint4* v4 = (const uint4*)s_p;

    unsigned hc[4][4], hp[4][4];
    #pragma unroll
    for (int r = 0; r < 4; r++) {
        uint4 A = v4[(r0 + r) * (IN_WP / 4) + cg];          // cols 4cg..4cg+3
        uint2 B = *(const uint2*)&s_p[(r0 + r) * IN_WP + 4 * cg + 4]; // +4,+5
        unsigned w[6] = { A.x, A.y, A.z, A.w, B.x, B.y };
        #pragma unroll
        for (int j = 0; j < 4; j++) {
            unsigned c = w[j] >> 8, p = w[j];
            fmin2(c, p, w[j + 1] >> 8, w[j + 1]);
            fmin2(c, p, w[j + 2] >> 8, w[j + 2]);
            hc[r][j] = c; hp[r][j] = p;
        }
    }

    float* op = out + (size_t)plane * (HO * WO);
    #pragma unroll
    for (int rr = 0; rr < 2; rr++) {
        const int orow = ty0 + r0 + rr;
        if (orow >= HO) continue;
        #pragma unroll
        for (int j = 0; j < 4; j++) {
            unsigned c = hc[rr][j], p = hp[rr][j];
            fmin2(c, p, hc[rr + 1][j], hp[rr + 1][j]);
            fmin2(c, p, hc[rr + 2][j], hp[rr + 2][j]);
            const int ocol = tx0 + 4 * cg + j;
            if (ocol < WO) op[orow * WO + ocol] = (float)(p & 0xFFu);
        }
    }
}

// ---------------------------------------------------------------------------
extern "C" void kernel_launch(void* const* d_in, const int* in_sizes, int n_in,
                              void* d_out, int out_size) {
    const float* x = (const float*)d_in[0];
    float* out = (float*)d_out;

    hist_kernel<<<HB, HTH>>>((const float4*)x);
    finalize_kernel<<<256, 128>>>();

    dim3 grid((WO + TW - 1) / TW, (HO + TH - 1) / TH, PLANES);  // (4, 8, 256)
    pool_kernel<<<grid, 256>>>(x, out);
}

// round 5
// speedup vs baseline: 2.3929x; 1.8363x over previous
#include <cuda_runtime.h>
#include <cstdint>

// Problem constants (fixed shapes): x = (8,32,256,256) fp32, K=3
#define PLANES 256            // B*C
#define H      256
#define W      256
#define HO     254
#define WO     254
#define N_ELEM (PLANES * H * W)     // 16,777,216
#define N4     (N_ELEM / 4)

// Hist config (lane-interleaved shared-atomic; 18.9us measured, keep)
#define HB 1024
#define HTH 256
#define HITER (N4 / (HB * HTH))   // 16 float4 per thread

// Pool config: full-width row strips
#define PTH 16                // output rows per block
#define PROWS (PTH + 2)       // input rows per block (18)

__device__ int g_counts[256];
__device__ int g_partial[256 * HB];   // [bin][block], 1 MB scratch

// ---------------------------------------------------------------------------
// Kernel 1: 256-bin histogram. 32 lane-interleaved shared sub-histograms
// (addr = bin*32 + lane) -> every warp-atomic is bank-conflict-free ATOMS.
// Per-block result written to g_partial (plain STG; no zeroing needed).
// ---------------------------------------------------------------------------
__global__ void __launch_bounds__(HTH) hist_kernel(const float4* __restrict__ x) {
    __shared__ int s_h[256 * 32];   // 32 KB
    const int tid = threadIdx.x;
    #pragma unroll
    for (int i = tid; i < 256 * 32; i += HTH) s_h[i] = 0;
    __syncthreads();

    const int lane = tid & 31;
    const float4* base = x + (size_t)blockIdx.x * (HTH * HITER);
    #pragma unroll 4
    for (int j = 0; j < HITER; j++) {
        float4 v = base[j * HTH + tid];
        atomicAdd(&s_h[(((int)v.x) & 255) * 32 + lane], 1);
        atomicAdd(&s_h[(((int)v.y) & 255) * 32 + lane], 1);
        atomicAdd(&s_h[(((int)v.z) & 255) * 32 + lane], 1);
        atomicAdd(&s_h[(((int)v.w) & 255) * 32 + lane], 1);
    }
    __syncthreads();

    // thread t reduces bin t's 32 lane-copies (staggered: conflict-free)
    int sum = 0;
    #pragma unroll
    for (int j = 0; j < 32; j++) {
        int i = (j + lane) & 31;
        sum += s_h[tid * 32 + i];
    }
    g_partial[tid * HB + blockIdx.x] = sum;
}

// ---------------------------------------------------------------------------
// Kernel 2: finalize — g_counts[bin] = sum over HB partials (overwrite each
// replay; deterministic, no zero kernel needed).
// ---------------------------------------------------------------------------
__global__ void __launch_bounds__(128) finalize_kernel() {
    const int bin = blockIdx.x;
    const int tid = threadIdx.x;
    int s = 0;
    #pragma unroll
    for (int k = 0; k < HB / 128; k++)
        s += g_partial[bin * HB + k * 128 + tid];
    #pragma unroll
    for (int o = 16; o; o >>= 1) s += __shfl_down_sync(0xFFFFFFFFu, s, o);
    __shared__ int ws[4];
    if ((tid & 31) == 0) ws[tid >> 5] = s;
    __syncthreads();
    if (tid == 0) g_counts[bin] = ws[0] + ws[1] + ws[2] + ws[3];
}

// ---------------------------------------------------------------------------
// Kernel 3: entropy pool, full-width row strips.
// Block = (plane, row-strip): 16 output rows x 254 cols from 18 input rows
// x 256 cols. Input slab is a contiguous float4 range (perfect coalescing).
// Shared tile holds packed (count<<8 | value); count clamped to 0xFFFFFF
// (safe: sum(counts)=2^24, so no other count can tie a clamped one).
// Thread c owns column c: horizontal 3-min per row (3 stride-1 LDS, order
// c,c+1,c+2 strict '<'), then rolling vertical 3-min in registers (order
// r,r+1,r+2 strict '<') == jnp.argmin first-occurrence tie-break.
// ---------------------------------------------------------------------------
__device__ __forceinline__ void fmin2(unsigned& c0, unsigned& p0,
                                      unsigned c1, unsigned p1) {
    if (c1 < c0) { c0 = c1; p0 = p1; }
}

__global__ void __launch_bounds__(256) pool_kernel(const float* __restrict__ x,
                                                   float* __restrict__ out) {
    __shared__ int s_cnt[256];
    __shared__ unsigned int s_pk[PROWS * W];   // 18 KB

    const int tid = threadIdx.x;
    s_cnt[tid] = g_counts[tid];
    __syncthreads();

    const int plane = blockIdx.y;
    const int r0 = blockIdx.x * PTH;                 // first output row
    const int nout = min(PTH, HO - r0);              // 16 (or 14 for last strip)
    const int rows_in = nout + 2;

    const float4* xp4 = (const float4*)(x + (size_t)plane * (H * W));
    const int base4 = r0 * (W / 4);                  // float4 index of strip start
    const int n4 = rows_in * (W / 4);                // float4 count (<= 1152)

    for (int i = tid; i < n4; i += 256) {
        float4 v = xp4[base4 + i];
        unsigned c0 = min((unsigned)s_cnt[((int)v.x) & 255], 0xFFFFFFu);
        unsigned c1 = min((unsigned)s_cnt[((int)v.y) & 255], 0xFFFFFFu);
        unsigned c2 = min((unsigned)s_cnt[((int)v.z) & 255], 0xFFFFFFu);
        unsigned c3 = min((unsigned)s_cnt[((int)v.w) & 255], 0xFFFFFFu);
        uint4 p;
        p.x = (c0 << 8) | (((int)v.x) & 255);
        p.y = (c1 << 8) | (((int)v.y) & 255);
        p.z = (c2 << 8) | (((int)v.z) & 255);
        p.w = (c3 << 8) | (((int)v.w) & 255);
        ((uint4*)s_pk)[i] = p;
    }
    __syncthreads();

    const int c = tid;
    if (c >= WO) return;

    // horizontal 3-min of row r at column c
    auto hmin = [&](int r, unsigned& hc, unsigned& hp) {
        const unsigned* row = &s_pk[r * W + c];
        unsigned w0 = row[0], w1 = row[1], w2 = row[2];
        hc = w0 >> 8; hp = w0;
        fmin2(hc, hp, w1 >> 8, w1);
        fmin2(hc, hp, w2 >> 8, w2);
    };

    unsigned hc0, hp0, hc1, hp1, hc2, hp2;
    hmin(0, hc0, hp0);
    hmin(1, hc1, hp1);

    float* op = out + (size_t)plane * (HO * WO) + (size_t)r0 * WO + c;
    for (int k = 0; k < nout; k++) {
        hmin(k + 2, hc2, hp2);
        unsigned bc = hc0, bp = hp0;
        fmin2(bc, bp, hc1, hp1);
        fmin2(bc, bp, hc2, hp2);
        op[k * WO] = (float)(bp & 0xFFu);
        hc0 = hc1; hp0 = hp1;
        hc1 = hc2; hp1 = hp2;
    }
}

// ---------------------------------------------------------------------------
extern "C" void kernel_launch(void* const* d_in, const int* in_sizes, int n_in,
                              void* d_out, int out_size) {
    const float* x = (const float*)d_in[0];
    float* out = (float*)d_out;

    hist_kernel<<<HB, HTH>>>((const float4*)x);
    finalize_kernel<<<256, 128>>>();

    dim3 grid((HO + PTH - 1) / PTH, PLANES);   // (16, 256) = 4096 blocks
    pool_kernel<<<grid, 256>>>(x, out);
}

// round 7
// speedup vs baseline: 2.6868x; 1.1228x over previous
#include <cuda_runtime.h>
#include <cstdint>

// Problem constants (fixed shapes): x = (8,32,256,256) fp32, K=3
#define PLANES 256            // B*C
#define H      256
#define W      256
#define HO     254
#define WO     254
#define N_ELEM (PLANES * H * W)     // 16,777,216
#define N32    (N_ELEM / 8)         // 32-byte units

// Hist config
#define HB 1024
#define HTH 256
#define HITER8 (N32 / (HB * HTH))   // 8 x 32-byte loads per thread (64 elems)

// Pool config: full-width row strips
#define PTH 16                // output rows per block
#define PROWS (PTH + 2)       // input rows per block (18)

__device__ unsigned int g_packed[256];     // (min(count,0xFFFFFF)<<8) | value
__device__ int g_partial[256 * HB];        // [bin][block], 1 MB scratch

// ---------------------------------------------------------------------------
// Kernel 1: 256-bin histogram, 16-bit packed shared counters (2 bins/word).
// addr = (v>>1)*32 + lane  ->  bank == lane: zero bank conflicts always.
// 16 KB smem -> 8 blocks/SM (full occupancy). Increment = atomicAdd of
// 1<<((v&1)*16); per-halfword max 512 (8 threads x 64 elems) -> no carry.
// Loads: 32-byte ld.global.nc.L2::evict_last.v4.b64 (x stays L2-resident
// for the pool pass; also halves LDG issue count).
// ---------------------------------------------------------------------------
__global__ void __launch_bounds__(HTH) hist_kernel(const float* __restrict__ x) {
    __shared__ unsigned int s_h[128 * 32];   // 16 KB
    const int tid = threadIdx.x;
    #pragma unroll
    for (int i = tid; i < 128 * 32; i += HTH) s_h[i] = 0u;
    __syncthreads();

    const int lane = tid & 31;
    const unsigned long long* base =
        (const unsigned long long*)x + (size_t)blockIdx.x * (HTH * HITER8) * 4;

    #pragma unroll
    for (int j = 0; j < HITER8; j++) {
        unsigned long long u0, u1, u2, u3;
        const unsigned long long* p = base + (size_t)(j * HTH + tid) * 4;
        asm volatile("ld.global.nc.L2::evict_last.v4.b64 {%0,%1,%2,%3}, [%4];"
                     : "=l"(u0), "=l"(u1), "=l"(u2), "=l"(u3) : "l"(p));
        #pragma unroll
        for (int q = 0; q < 4; q++) {
            unsigned long long u = (q == 0) ? u0 : (q == 1) ? u1 : (q == 2) ? u2 : u3;
            int a = ((int)__uint_as_float((unsigned)u)) & 255;
            int b = ((int)__uint_as_float((unsigned)(u >> 32))) & 255;
            atomicAdd(&s_h[(a >> 1) * 32 + lane], 1u << ((a & 1) << 4));
            atomicAdd(&s_h[(b >> 1) * 32 + lane], 1u << ((b & 1) << 4));
        }
    }
    __syncthreads();

    // thread t (<128) reduces word-row t: 32 lane copies, staggered (bank-free)
    if (tid < 128) {
        unsigned lo = 0, hi = 0;
        #pragma unroll
        for (int j = 0; j < 32; j++) {
            unsigned w = s_h[tid * 32 + ((j + lane) & 31)];
            lo += w & 0xFFFFu;
            hi += w >> 16;
        }
        __stcs(&g_partial[(2 * tid + 0) * HB + blockIdx.x], (int)lo);
        __stcs(&g_partial[(2 * tid + 1) * HB + blockIdx.x], (int)hi);
    }
}

// ---------------------------------------------------------------------------
// Kernel 2: finalize — overwrite g_packed[bin] with (min(cnt,0xFFFFFF)<<8)|bin.
// Deterministic per replay (pure overwrite; no zeroing needed anywhere).
// Clamp safe: sum(counts)=2^24 so no other count can tie a clamped one.
// ---------------------------------------------------------------------------
__global__ void __launch_bounds__(128) finalize_kernel() {
    const int bin = blockIdx.x;
    const int tid = threadIdx.x;
    int s = 0;
    #pragma unroll
    for (int k = 0; k < HB / 128; k++)
        s += g_partial[bin * HB + k * 128 + tid];
    #pragma unroll
    for (int o = 16; o; o >>= 1) s += __shfl_down_sync(0xFFFFFFFFu, s, o);
    __shared__ int ws[4];
    if ((tid & 31) == 0) ws[tid >> 5] = s;
    __syncthreads();
    if (tid == 0) {
        unsigned cnt = (unsigned)(ws[0] + ws[1] + ws[2] + ws[3]);
        if (cnt > 0xFFFFFFu) cnt = 0xFFFFFFu;
        g_packed[bin] = (cnt << 8) | (unsigned)bin;
    }
}

// ---------------------------------------------------------------------------
// Kernel 3: entropy pool, full-width row strips (16 out rows x 254 cols from
// 18 in rows x 256 cols; contiguous float4 slab -> perfect coalescing).
// Phase 1: packed-table lookup per element (1 LDS, no ALU repack), store tile.
// Phase 2: thread-per-column, horizontal 3-min then rolling vertical 3-min,
// strict '<' in row-then-col order == jnp.argmin first-occurrence tie-break.
// x read via __ldcs (L2-resident from hist, dead after), out via __stcs.
// ---------------------------------------------------------------------------
__device__ __forceinline__ void fmin2(unsigned& c0, unsigned& p0,
                                      unsigned c1, unsigned p1) {
    if (c1 < c0) { c0 = c1; p0 = p1; }
}

__global__ void __launch_bounds__(256) pool_kernel(const float* __restrict__ x,
                                                   float* __restrict__ out) {
    __shared__ unsigned s_tbl[256];
    __shared__ unsigned s_pk[PROWS * W];   // 18 KB

    const int tid = threadIdx.x;
    s_tbl[tid] = g_packed[tid];
    __syncthreads();

    const int plane = blockIdx.y;
    const int r0 = blockIdx.x * PTH;
    const int nout = min(PTH, HO - r0);
    const int rows_in = nout + 2;

    const float4* xp4 = (const float4*)(x + (size_t)plane * (H * W));
    const int base4 = r0 * (W / 4);
    const int n4 = rows_in * (W / 4);

    for (int i = tid; i < n4; i += 256) {
        float4 v = __ldcs(xp4 + base4 + i);
        uint4 p;
        p.x = s_tbl[((int)v.x) & 255];
        p.y = s_tbl[((int)v.y) & 255];
        p.z = s_tbl[((int)v.z) & 255];
        p.w = s_tbl[((int)v.w) & 255];
        ((uint4*)s_pk)[i] = p;
    }
    __syncthreads();

    const int c = tid;
    if (c >= WO) return;

    auto hmin = [&](int r, unsigned& hc, unsigned& hp) {
        const unsigned* row = &s_pk[r * W + c];
        unsigned w0 = row[0], w1 = row[1], w2 = row[2];
        hc = w0 >> 8; hp = w0;
        fmin2(hc, hp, w1 >> 8, w1);
        fmin2(hc, hp, w2 >> 8, w2);
    };

    unsigned hc0, hp0, hc1, hp1, hc2, hp2;
    hmin(0, hc0, hp0);
    hmin(1, hc1, hp1);

    float* op = out + (size_t)plane * (HO * WO) + (size_t)r0 * WO + c;
    for (int k = 0; k < nout; k++) {
        hmin(k + 2, hc2, hp2);
        unsigned bc = hc0, bp = hp0;
        fmin2(bc, bp, hc1, hp1);
        fmin2(bc, bp, hc2, hp2);
        __stcs(&op[k * WO], (float)(bp & 0xFFu));
        hc0 = hc1; hp0 = hp1;
        hc1 = hc2; hp1 = hp2;
    }
}

// ---------------------------------------------------------------------------
extern "C" void kernel_launch(void* const* d_in, const int* in_sizes, int n_in,
                              void* d_out, int out_size) {
    const float* x = (const float*)d_in[0];
    float* out = (float*)d_out;

    hist_kernel<<<HB, HTH>>>(x);
    finalize_kernel<<<256, 128>>>();

    dim3 grid((HO + PTH - 1) / PTH, PLANES);   // (16, 256) = 4096 blocks
    pool_kernel<<<grid, 256>>>(x, out);
}